// round 1
// baseline (speedup 1.0000x reference)
#include <cuda_runtime.h>
#include <math.h>

#define BB 512
#define TT 2048
#define CC 64

__device__ int   g_i0[TT];
__device__ float g_w0[TT];
__device__ float g_w1[TT];
__device__ float g_ca[BB];
__device__ float g_sa[BB];
__device__ float g_mask[CC];

// One-block prep: cumsum/normalize warp_noise -> (i0, w0, w1) per t,
// per-batch rotation cos/sin, channel dropout mask.
__global__ void __launch_bounds__(512) prep_kernel(
    const float* __restrict__ scale_u,
    const float* __restrict__ warp_noise,
    const float* __restrict__ angle_u,
    const float* __restrict__ chmask_u)
{
    __shared__ float cum[TT];
    __shared__ float chunk[256];
    const int tid = threadIdx.x;          // 512 threads
    const float k = 0.2f / (float)TT;     // TW_SIGMA / T

    float loc[8];
    if (tid < 256) {
        float run = 0.f;
        #pragma unroll
        for (int i = 0; i < 8; i++) {
            run += warp_noise[tid * 8 + i] * k;
            loc[i] = run;
        }
        chunk[tid] = run;
    }
    __syncthreads();
    if (tid == 0) {
        float a = 0.f;
        for (int j = 0; j < 256; j++) { float v = chunk[j]; chunk[j] = a; a += v; }
    }
    __syncthreads();
    if (tid < 256) {
        float off = chunk[tid];
        #pragma unroll
        for (int i = 0; i < 8; i++) cum[tid * 8 + i] = off + loc[i];
    }
    __syncthreads();

    const float c0    = cum[0];
    const float denom = (cum[TT - 1] - c0) + 1e-8f;
    const float scale = 0.9f + scale_u[0] * 0.2f;

    if (tid < 256) {
        #pragma unroll
        for (int i = 0; i < 8; i++) {
            int t = tid * 8 + i;
            float w  = (cum[t] - c0) / denom;
            float tw = (float)t / (float)(TT - 1) + 0.2f * w;
            tw = fminf(fmaxf(tw, 0.f), 1.f);
            float pos = tw * (float)(TT - 1);
            int i0 = (int)floorf(pos);
            i0 = min(max(i0, 0), TT - 2);
            float frac = pos - (float)i0;
            g_i0[t] = i0;
            g_w0[t] = scale * (1.f - frac);
            g_w1[t] = scale * frac;
        }
    }

    // Per-batch rotation (512 threads == B)
    {
        float ang = angle_u[tid] * 6.283185307179586f - 3.141592653589793f;
        g_ca[tid] = cosf(ang);
        g_sa[tid] = sinf(ang);
    }
    if (tid < CC) g_mask[tid] = (chmask_u[tid] > 0.1f) ? 1.f : 0.f;
}

// Fully fused main pass: one float4 (4 channels) per thread, 16 threads per (b,t) row.
__global__ void __launch_bounds__(256) aug_kernel(
    const float4* __restrict__ x,
    const float4* __restrict__ nz,
    float4* __restrict__ out)
{
    const int gid  = blockIdx.x * 256 + threadIdx.x;
    const int row  = gid >> 4;            // b*T + t
    const int lane = gid & 15;            // which float4 in the 64-channel row
    const int t    = row & (TT - 1);
    const int b    = row >> 11;           // T = 2048 = 2^11

    const int   i0 = g_i0[t];
    const float w0 = g_w0[t];
    const float w1 = g_w1[t];

    const size_t base = ((size_t)b * TT + (size_t)i0) * 16 + (size_t)lane;
    const float4 x0 = __ldg(x  + base);
    const float4 x1 = __ldg(x  + base + 16);
    const float4 n0 = __ldg(nz + base);
    const float4 n1 = __ldg(nz + base + 16);

    const float J = 0.01f;
    float4 v;
    v.x = w0 * fmaf(J, n0.x, x0.x) + w1 * fmaf(J, n1.x, x1.x);
    v.y = w0 * fmaf(J, n0.y, x0.y) + w1 * fmaf(J, n1.y, x1.y);
    v.z = w0 * fmaf(J, n0.z, x0.z) + w1 * fmaf(J, n1.z, x1.z);
    v.w = w0 * fmaf(J, n0.w, x0.w) + w1 * fmaf(J, n1.w, x1.w);

    if (lane == 0) {  // channels 0,1 rotation
        const float ca = g_ca[b], sa = g_sa[b];
        const float r0 = ca * v.x - sa * v.y;
        const float r1 = sa * v.x + ca * v.y;
        v.x = r0; v.y = r1;
    }

    const float4 m = reinterpret_cast<const float4*>(g_mask)[lane];
    v.x *= m.x; v.y *= m.y; v.z *= m.z; v.w *= m.w;

    out[(size_t)row * 16 + lane] = v;
}

extern "C" void kernel_launch(void* const* d_in, const int* in_sizes, int n_in,
                              void* d_out, int out_size)
{
    const float* x        = (const float*)d_in[0];
    const float* noise    = (const float*)d_in[1];
    const float* scale_u  = (const float*)d_in[2];
    const float* warp_n   = (const float*)d_in[3];
    const float* angle_u  = (const float*)d_in[4];
    const float* chmask_u = (const float*)d_in[5];
    float* out = (float*)d_out;

    prep_kernel<<<1, 512>>>(scale_u, warp_n, angle_u, chmask_u);

    // B*T*C / 4 floats per thread = 512*2048*16 threads
    const int total_threads = BB * TT * 16;
    aug_kernel<<<total_threads / 256, 256>>>(
        (const float4*)x, (const float4*)noise, (float4*)out);
}